// round 2
// baseline (speedup 1.0000x reference)
#include <cuda_runtime.h>

#define KBINS 8
#define BVAL 3.0f
#define DIMN 32
#define HID 32
#define LNUM 31
#define NP 23
#define NPP 24          // padded
#define MIN_BW 1e-3f
#define MIN_D 1e-3f
#define BATCH 65536
#define CPAD 0.5397416f  // log(exp(1-MIN_D)-1)

// float4 counts per layer
#define W1_F4 248   // 31*32/4
#define W2_F4 256   // 32*32/4
#define W3_F4 192   // 32*24/4 (padded)
#define WBUF_F4 (W1_F4 + W2_F4 + W3_F4)   // 696

__device__ __forceinline__ float fast_tanh(float x) {
    float e = __expf(2.0f * x);
    return 1.0f - __fdividef(2.0f, e + 1.0f);
}

__device__ __forceinline__ float softplusf(float x) {
    return fmaxf(x, 0.0f) + __logf(1.0f + __expf(-fabsf(x)));
}

// softmax with max-subtraction (first stage: unbounded inputs)
__device__ __forceinline__ void softmax8(const float* p, float scale, float* out) {
    float m = p[0];
#pragma unroll
    for (int i = 1; i < KBINS; i++) m = fmaxf(m, p[i]);
    float s = 0.0f;
#pragma unroll
    for (int i = 0; i < KBINS; i++) { out[i] = __expf(p[i] - m); s += out[i]; }
    float inv = __fdividef(scale, s);
#pragma unroll
    for (int i = 0; i < KBINS; i++) out[i] *= inv;
}

// softmax without max-subtraction (inputs known to lie in (0, 2B] -> exp safe)
__device__ __forceinline__ void softmax8_nm(const float* p, float scale, float* out) {
    float s = 0.0f;
#pragma unroll
    for (int i = 0; i < KBINS; i++) { out[i] = __expf(p[i]); s += out[i]; }
    float inv = __fdividef(scale, s);
#pragma unroll
    for (int i = 0; i < KBINS; i++) out[i] *= inv;
}

__device__ __forceinline__ float spline_fwd(float xin, const float* p, float* ldo) {
    float wu[KBINS], w_[KBINS];
    softmax8(p, 2.0f * BVAL, wu);
    softmax8_nm(wu, 1.0f - MIN_BW * KBINS, w_);
#pragma unroll
    for (int i = 0; i < KBINS; i++) w_[i] += MIN_BW;
    float hu[KBINS], h_[KBINS];
    softmax8(p + KBINS, 2.0f * BVAL, hu);
    softmax8_nm(hu, 1.0f - MIN_BW * KBINS, h_);
#pragma unroll
    for (int i = 0; i < KBINS; i++) h_[i] += MIN_BW;

    float cw[KBINS + 1], ch[KBINS + 1];
    cw[0] = -BVAL; ch[0] = -BVAL;
    {
        float c = 0.0f;
#pragma unroll
        for (int k = 0; k < KBINS; k++) { c += w_[k]; cw[k + 1] = 2.0f * BVAL * c - BVAL; }
        cw[KBINS] = BVAL;
        c = 0.0f;
#pragma unroll
        for (int k = 0; k < KBINS; k++) { c += h_[k]; ch[k + 1] = 2.0f * BVAL * c - BVAL; }
        ch[KBINS] = BVAL;
    }

    float dv[KBINS + 1];
    {
        float de = MIN_D + softplusf(CPAD);
        dv[0] = de; dv[KBINS] = de;
#pragma unroll
        for (int j = 0; j < KBINS - 1; j++)
            dv[j + 1] = MIN_D + softplusf(softplusf(p[2 * KBINS + j]));
    }

    bool inside = (xin >= -BVAL) && (xin <= BVAL);
    float xc = fminf(fmaxf(xin, -BVAL), BVAL);

    float in_cw = cw[0], in_ch = ch[0];
    float in_w = cw[1] - cw[0], in_h = ch[1] - ch[0];
    float d0 = dv[0], d1 = dv[1];
#pragma unroll
    for (int k = 1; k < KBINS; k++) {
        if (xc >= cw[k]) {
            in_cw = cw[k]; in_ch = ch[k];
            in_w = cw[k + 1] - cw[k]; in_h = ch[k + 1] - ch[k];
            d0 = dv[k]; d1 = dv[k + 1];
        }
    }

    float invw = __fdividef(1.0f, in_w);
    float delta = in_h * invw;
    float th = (xc - in_cw) * invw;
    float tt = th * (1.0f - th);
    float num = in_h * (delta * th * th + d0 * tt);
    float den = delta + (d0 + d1 - 2.0f * delta) * tt;
    float outv = in_ch + __fdividef(num, den);
    float omt = 1.0f - th;
    float dnum = delta * delta * (d1 * th * th + 2.0f * delta * tt + d0 * omt * omt);
    float ld = __logf(dnum) - 2.0f * __logf(den);

    *ldo = inside ? ld : 0.0f;
    return inside ? outv : xin;
}

__device__ __forceinline__ void stage_layer(
    int l, int t, float4* wb, float* bb,
    const float* __restrict__ w1, const float* __restrict__ b1,
    const float* __restrict__ w2, const float* __restrict__ b2,
    const float* __restrict__ w3, const float* __restrict__ b3)
{
    const float4* g1 = (const float4*)(w1 + l * 992);
    for (int i = t; i < W1_F4; i += 128) wb[i] = g1[i];
    const float4* g2 = (const float4*)(w2 + l * 1024);
    for (int i = t; i < W2_F4; i += 128) wb[W1_F4 + i] = g2[i];
    float* w3f = (float*)(wb + W1_F4 + W2_F4);
    for (int i = t; i < 736; i += 128) {
        int r = i / 23, c = i - r * 23;
        w3f[r * NPP + c] = w3[l * 736 + i];
    }
    if (t < 32) {
        w3f[t * NPP + 23] = 0.0f;
        bb[t]      = b1[l * 32 + t];
        bb[32 + t] = b2[l * 32 + t];
    }
    if (t < NPP) bb[64 + t] = (t < NP) ? b3[l * NP + t] : 0.0f;
}

__global__ __launch_bounds__(128) void nsf_ar_kernel(
    const float* __restrict__ x, const float* __restrict__ init_param,
    const float* __restrict__ w1, const float* __restrict__ b1,
    const float* __restrict__ w2, const float* __restrict__ b2,
    const float* __restrict__ w3, const float* __restrict__ b3,
    float* __restrict__ zout, float* __restrict__ ldout, int write_ld)
{
    __shared__ float xs[128][33];
    __shared__ float4 wbuf[2][WBUF_F4];
    __shared__ float bbuf[2][96];     // b1:32, b2:32, b3:24(padded)

    const int t = threadIdx.x;
    const int b0 = blockIdx.x * 128;

    // stage x tile (coalesced, vectorized)
    {
        const float4* gx = (const float4*)(x + (size_t)b0 * 32);
        for (int i = t; i < 128 * 8; i += 128) {
            float4 v = gx[i];
            int row = i >> 3, c4 = (i & 7) << 2;
            xs[row][c4 + 0] = v.x; xs[row][c4 + 1] = v.y;
            xs[row][c4 + 2] = v.z; xs[row][c4 + 3] = v.w;
        }
    }
    // stage layer 0 into buf 0
    stage_layer(0, t, wbuf[0], bbuf[0], w1, b1, w2, b2, w3, b3);
    __syncthreads();

    const int b = b0 + t;
    float ldacc;
    {
        float p[NP];
#pragma unroll
        for (int j = 0; j < NP; j++) p[j] = init_param[j];
        float ld;
        zout[(size_t)b * DIMN] = spline_fwd(xs[t][0], p, &ld);
        ldacc = ld;
    }

    for (int l = 0; l < LNUM; l++) {
        const int cur = l & 1;
        // prefetch next layer into the other buffer (safe: its last readers
        // finished before the barrier at the end of the previous iteration)
        if (l + 1 < LNUM)
            stage_layer(l + 1, t, wbuf[cur ^ 1], bbuf[cur ^ 1],
                        w1, b1, w2, b2, w3, b3);

        const float4* w1v = wbuf[cur];
        const float4* w2v = wbuf[cur] + W1_F4;
        const float4* w3v = wbuf[cur] + W1_F4 + W2_F4;
        const float*  bb  = bbuf[cur];

        // h1 = tanh(x[:, :l+1] @ w1 + b1)  (causal: d <= l)
        float h1[HID];
#pragma unroll
        for (int h = 0; h < HID; h++) h1[h] = bb[h];
        for (int d = 0; d <= l; d++) {
            float xd = xs[t][d];
#pragma unroll
            for (int h4 = 0; h4 < 8; h4++) {
                float4 w = w1v[d * 8 + h4];
                h1[h4 * 4 + 0] = fmaf(xd, w.x, h1[h4 * 4 + 0]);
                h1[h4 * 4 + 1] = fmaf(xd, w.y, h1[h4 * 4 + 1]);
                h1[h4 * 4 + 2] = fmaf(xd, w.z, h1[h4 * 4 + 2]);
                h1[h4 * 4 + 3] = fmaf(xd, w.w, h1[h4 * 4 + 3]);
            }
        }
#pragma unroll
        for (int h = 0; h < HID; h++) h1[h] = fast_tanh(h1[h]);

        // h2 = tanh(h1 @ w2 + b2)
        float h2[HID];
#pragma unroll
        for (int h = 0; h < HID; h++) h2[h] = bb[32 + h];
#pragma unroll 4
        for (int d = 0; d < HID; d++) {
            float v = h1[d];
#pragma unroll
            for (int h4 = 0; h4 < 8; h4++) {
                float4 w = w2v[d * 8 + h4];
                h2[h4 * 4 + 0] = fmaf(v, w.x, h2[h4 * 4 + 0]);
                h2[h4 * 4 + 1] = fmaf(v, w.y, h2[h4 * 4 + 1]);
                h2[h4 * 4 + 2] = fmaf(v, w.z, h2[h4 * 4 + 2]);
                h2[h4 * 4 + 3] = fmaf(v, w.w, h2[h4 * 4 + 3]);
            }
        }
#pragma unroll
        for (int h = 0; h < HID; h++) h2[h] = fast_tanh(h2[h]);

        // p = h2 @ w3 + b3  (padded to 24)
        float p[NPP];
#pragma unroll
        for (int j = 0; j < NPP; j++) p[j] = bb[64 + j];
#pragma unroll 4
        for (int d = 0; d < HID; d++) {
            float v = h2[d];
#pragma unroll
            for (int j4 = 0; j4 < 6; j4++) {
                float4 w = w3v[d * 6 + j4];
                p[j4 * 4 + 0] = fmaf(v, w.x, p[j4 * 4 + 0]);
                p[j4 * 4 + 1] = fmaf(v, w.y, p[j4 * 4 + 1]);
                p[j4 * 4 + 2] = fmaf(v, w.z, p[j4 * 4 + 2]);
                p[j4 * 4 + 3] = fmaf(v, w.w, p[j4 * 4 + 3]);
            }
        }

        float ld;
        zout[(size_t)b * DIMN + l + 1] = spline_fwd(xs[t][l + 1], p, &ld);
        ldacc += ld;

        __syncthreads();   // publish prefetched buffer / protect overwrite
    }

    if (write_ld) ldout[b] = ldacc;
}

extern "C" void kernel_launch(void* const* d_in, const int* in_sizes, int n_in,
                              void* d_out, int out_size) {
    const float* x          = (const float*)d_in[0];
    const float* init_param = (const float*)d_in[1];
    const float* w1 = (const float*)d_in[2];
    const float* b1 = (const float*)d_in[3];
    const float* w2 = (const float*)d_in[4];
    const float* b2 = (const float*)d_in[5];
    const float* w3 = (const float*)d_in[6];
    const float* b3 = (const float*)d_in[7];

    float* out = (float*)d_out;
    int write_ld = (out_size >= BATCH * DIMN + BATCH) ? 1 : 0;

    nsf_ar_kernel<<<BATCH / 128, 128>>>(x, init_param, w1, b1, w2, b2, w3, b3,
                                        out, out + (size_t)BATCH * DIMN, write_ld);
}

// round 3
// speedup vs baseline: 1.0234x; 1.0234x over previous
#include <cuda_runtime.h>

#define KBINS 8
#define BVAL 3.0f
#define DIMN 32
#define HID 32
#define LNUM 31
#define NP 23
#define NPP 24
#define MIN_BW 1e-3f
#define MIN_D 1e-3f
#define BATCH 65536
#define CPAD 0.5397416f  // log(exp(1-MIN_D)-1)

#define W1_F4 248   // 31*32/4
#define W2_F4 256   // 32*32/4
#define W3_F4 192   // 32*24/4 (padded)
#define WBUF_F4 (W1_F4 + W2_F4 + W3_F4)

__device__ __forceinline__ float fast_tanh(float x) {
    float e = __expf(2.0f * x);
    return 1.0f - __fdividef(2.0f, e + 1.0f);
}

__device__ __forceinline__ float softplusf(float x) {
    return fmaxf(x, 0.0f) + __logf(1.0f + __expf(-fabsf(x)));
}

__device__ __forceinline__ void softmax8(const float* p, float scale, float* out) {
    float m = p[0];
#pragma unroll
    for (int i = 1; i < KBINS; i++) m = fmaxf(m, p[i]);
    float s = 0.0f;
#pragma unroll
    for (int i = 0; i < KBINS; i++) { out[i] = __expf(p[i] - m); s += out[i]; }
    float inv = __fdividef(scale, s);
#pragma unroll
    for (int i = 0; i < KBINS; i++) out[i] *= inv;
}

// inputs known to lie in (0, 2B] -> exp safe without max-subtraction
__device__ __forceinline__ void softmax8_nm(const float* p, float scale, float* out) {
    float s = 0.0f;
#pragma unroll
    for (int i = 0; i < KBINS; i++) { out[i] = __expf(p[i]); s += out[i]; }
    float inv = __fdividef(scale, s);
#pragma unroll
    for (int i = 0; i < KBINS; i++) out[i] *= inv;
}

__device__ __forceinline__ float spline_fwd(float xin, const float* p, float* ldo) {
    float cw[KBINS + 1], ch[KBINS + 1];
    {
        float wu[KBINS], w_[KBINS];
        softmax8(p, 2.0f * BVAL, wu);
        softmax8_nm(wu, 1.0f - MIN_BW * KBINS, w_);
        cw[0] = -BVAL;
        float c = 0.0f;
#pragma unroll
        for (int k = 0; k < KBINS; k++) {
            c += w_[k] + MIN_BW;
            cw[k + 1] = 2.0f * BVAL * c - BVAL;
        }
        cw[KBINS] = BVAL;
    }
    {
        float hu[KBINS], h_[KBINS];
        softmax8(p + KBINS, 2.0f * BVAL, hu);
        softmax8_nm(hu, 1.0f - MIN_BW * KBINS, h_);
        ch[0] = -BVAL;
        float c = 0.0f;
#pragma unroll
        for (int k = 0; k < KBINS; k++) {
            c += h_[k] + MIN_BW;
            ch[k + 1] = 2.0f * BVAL * c - BVAL;
        }
        ch[KBINS] = BVAL;
    }

    float dv[KBINS + 1];
    {
        float de = MIN_D + softplusf(CPAD);
        dv[0] = de; dv[KBINS] = de;
#pragma unroll
        for (int j = 0; j < KBINS - 1; j++)
            dv[j + 1] = MIN_D + softplusf(softplusf(p[2 * KBINS + j]));
    }

    bool inside = (xin >= -BVAL) && (xin <= BVAL);
    float xc = fminf(fmaxf(xin, -BVAL), BVAL);

    float in_cw = cw[0], in_ch = ch[0];
    float in_w = cw[1] - cw[0], in_h = ch[1] - ch[0];
    float d0 = dv[0], d1 = dv[1];
#pragma unroll
    for (int k = 1; k < KBINS; k++) {
        if (xc >= cw[k]) {
            in_cw = cw[k]; in_ch = ch[k];
            in_w = cw[k + 1] - cw[k]; in_h = ch[k + 1] - ch[k];
            d0 = dv[k]; d1 = dv[k + 1];
        }
    }

    float invw = __fdividef(1.0f, in_w);
    float delta = in_h * invw;
    float th = (xc - in_cw) * invw;
    float tt = th * (1.0f - th);
    float num = in_h * (delta * th * th + d0 * tt);
    float den = delta + (d0 + d1 - 2.0f * delta) * tt;
    float outv = in_ch + __fdividef(num, den);
    float omt = 1.0f - th;
    float dnum = delta * delta * (d1 * th * th + 2.0f * delta * tt + d0 * omt * omt);
    float ld = __logf(dnum) - 2.0f * __logf(den);

    *ldo = inside ? ld : 0.0f;
    return inside ? outv : xin;
}

__global__ __launch_bounds__(128, 4) void nsf_ar_kernel(
    const float* __restrict__ x, const float* __restrict__ init_param,
    const float* __restrict__ w1, const float* __restrict__ b1,
    const float* __restrict__ w2, const float* __restrict__ b2,
    const float* __restrict__ w3, const float* __restrict__ b3,
    float* __restrict__ zout, float* __restrict__ ldout, int write_ld)
{
    __shared__ float xs[128][33];
    __shared__ float zs[128][33];
    __shared__ float4 wbuf[WBUF_F4];
    __shared__ float bbuf[96];       // b1:32, b2:32, b3:24

    const int t = threadIdx.x;
    const int b0 = blockIdx.x * 128;

    // stage x tile (coalesced, vectorized)
    {
        const float4* gx = (const float4*)(x + (size_t)b0 * 32);
        for (int i = t; i < 128 * 8; i += 128) {
            float4 v = gx[i];
            int row = i >> 3, c4 = (i & 7) << 2;
            xs[row][c4 + 0] = v.x; xs[row][c4 + 1] = v.y;
            xs[row][c4 + 2] = v.z; xs[row][c4 + 3] = v.w;
        }
    }
    __syncthreads();

    float ldacc;
    {
        float p[NP];
#pragma unroll
        for (int j = 0; j < NP; j++) p[j] = init_param[j];   // uniform broadcast
        float ld;
        zs[t][0] = spline_fwd(xs[t][0], p, &ld);
        ldacc = ld;
    }

    for (int l = 0; l < LNUM; l++) {
        __syncthreads();
        // stage layer-l weights (single buffer)
        {
            const float4* g1 = (const float4*)(w1 + l * 992);
            for (int i = t; i < W1_F4; i += 128) wbuf[i] = g1[i];
            const float4* g2 = (const float4*)(w2 + l * 1024);
            for (int i = t; i < W2_F4; i += 128) wbuf[W1_F4 + i] = g2[i];
            float* w3f = (float*)(wbuf + W1_F4 + W2_F4);
            for (int i = t; i < 736; i += 128) {
                int r = i / 23, c = i - r * 23;
                w3f[r * NPP + c] = w3[l * 736 + i];
            }
            if (t < 32) {
                w3f[t * NPP + 23] = 0.0f;
                bbuf[t]      = b1[l * 32 + t];
                bbuf[32 + t] = b2[l * 32 + t];
            }
            if (t < NPP) bbuf[64 + t] = (t < NP) ? b3[l * NP + t] : 0.0f;
        }
        __syncthreads();

        const float4* w1v = wbuf;
        const float4* w2v = wbuf + W1_F4;
        const float4* w3v = wbuf + W1_F4 + W2_F4;

        // h1 = tanh(x[:, :l+1] @ w1 + b1)   (causal: d <= l)
        float h1[HID];
#pragma unroll
        for (int h = 0; h < HID; h++) h1[h] = bbuf[h];
        for (int d = 0; d <= l; d++) {
            float xd = xs[t][d];
#pragma unroll
            for (int h4 = 0; h4 < 8; h4++) {
                float4 w = w1v[d * 8 + h4];
                h1[h4 * 4 + 0] = fmaf(xd, w.x, h1[h4 * 4 + 0]);
                h1[h4 * 4 + 1] = fmaf(xd, w.y, h1[h4 * 4 + 1]);
                h1[h4 * 4 + 2] = fmaf(xd, w.z, h1[h4 * 4 + 2]);
                h1[h4 * 4 + 3] = fmaf(xd, w.w, h1[h4 * 4 + 3]);
            }
        }
#pragma unroll
        for (int h = 0; h < HID; h++) h1[h] = fast_tanh(h1[h]);

        // h2 = tanh(h1 @ w2 + b2)
        float h2[HID];
#pragma unroll
        for (int h = 0; h < HID; h++) h2[h] = bbuf[32 + h];
#pragma unroll
        for (int d = 0; d < HID; d++) {
            float v = h1[d];
#pragma unroll
            for (int h4 = 0; h4 < 8; h4++) {
                float4 w = w2v[d * 8 + h4];
                h2[h4 * 4 + 0] = fmaf(v, w.x, h2[h4 * 4 + 0]);
                h2[h4 * 4 + 1] = fmaf(v, w.y, h2[h4 * 4 + 1]);
                h2[h4 * 4 + 2] = fmaf(v, w.z, h2[h4 * 4 + 2]);
                h2[h4 * 4 + 3] = fmaf(v, w.w, h2[h4 * 4 + 3]);
            }
        }
#pragma unroll
        for (int h = 0; h < HID; h++) h2[h] = fast_tanh(h2[h]);

        // p = h2 @ w3 + b3  (padded to 24 cols)
        float p[NPP];
#pragma unroll
        for (int j = 0; j < NPP; j++) p[j] = bbuf[64 + j];
#pragma unroll
        for (int d = 0; d < HID; d++) {
            float v = h2[d];
#pragma unroll
            for (int j4 = 0; j4 < 6; j4++) {
                float4 w = w3v[d * 6 + j4];
                p[j4 * 4 + 0] = fmaf(v, w.x, p[j4 * 4 + 0]);
                p[j4 * 4 + 1] = fmaf(v, w.y, p[j4 * 4 + 1]);
                p[j4 * 4 + 2] = fmaf(v, w.z, p[j4 * 4 + 2]);
                p[j4 * 4 + 3] = fmaf(v, w.w, p[j4 * 4 + 3]);
            }
        }

        float ld;
        zs[t][l + 1] = spline_fwd(xs[t][l + 1], p, &ld);
        ldacc += ld;
    }

    if (write_ld) ldout[b0 + t] = ldacc;

    // coalesced z epilogue
    __syncthreads();
    {
        float4* gz = (float4*)(zout + (size_t)b0 * 32);
        for (int i = t; i < 128 * 8; i += 128) {
            int row = i >> 3, c4 = (i & 7) << 2;
            float4 v;
            v.x = zs[row][c4 + 0]; v.y = zs[row][c4 + 1];
            v.z = zs[row][c4 + 2]; v.w = zs[row][c4 + 3];
            gz[i] = v;
        }
    }
}

extern "C" void kernel_launch(void* const* d_in, const int* in_sizes, int n_in,
                              void* d_out, int out_size) {
    const float* x          = (const float*)d_in[0];
    const float* init_param = (const float*)d_in[1];
    const float* w1 = (const float*)d_in[2];
    const float* b1 = (const float*)d_in[3];
    const float* w2 = (const float*)d_in[4];
    const float* b2 = (const float*)d_in[5];
    const float* w3 = (const float*)d_in[6];
    const float* b3 = (const float*)d_in[7];

    float* out = (float*)d_out;
    int write_ld = (out_size >= BATCH * DIMN + BATCH) ? 1 : 0;

    nsf_ar_kernel<<<BATCH / 128, 128>>>(x, init_param, w1, b1, w2, b2, w3, b3,
                                        out, out + (size_t)BATCH * DIMN, write_ld);
}

// round 4
// speedup vs baseline: 1.7217x; 1.6823x over previous
#include <cuda_runtime.h>

#define KBINS 8
#define BVAL 3.0f
#define DIMN 32
#define HID 32
#define LNUM 31
#define NP 23
#define MIN_BW 1e-3f
#define MIN_D 1e-3f
#define BATCH 65536
#define CPAD 0.5397416f  // log(exp(1-MIN_D)-1)

__device__ __forceinline__ float fast_tanh(float x) {
    float e = __expf(2.0f * x);
    return 1.0f - __fdividef(2.0f, e + 1.0f);
}

__device__ __forceinline__ float softplusf(float x) {
    return fmaxf(x, 0.0f) + __logf(1.0f + __expf(-fabsf(x)));
}

__device__ __forceinline__ void softmax8(const float* p, float scale, float* out) {
    float m = p[0];
#pragma unroll
    for (int i = 1; i < KBINS; i++) m = fmaxf(m, p[i]);
    float s = 0.0f;
#pragma unroll
    for (int i = 0; i < KBINS; i++) { out[i] = __expf(p[i] - m); s += out[i]; }
    float inv = __fdividef(scale, s);
#pragma unroll
    for (int i = 0; i < KBINS; i++) out[i] *= inv;
}

// second-stage softmax: inputs in (0, 2B] -> no max subtraction needed
__device__ __forceinline__ void softmax8_nm(const float* p, float scale, float* out) {
    float s = 0.0f;
#pragma unroll
    for (int i = 0; i < KBINS; i++) { out[i] = __expf(p[i]); s += out[i]; }
    float inv = __fdividef(scale, s);
#pragma unroll
    for (int i = 0; i < KBINS; i++) out[i] *= inv;
}

__device__ __forceinline__ float spline_fwd(float xin, const float* p, float* ldo) {
    float cw[KBINS + 1], ch[KBINS + 1];
    {
        float wu[KBINS], w_[KBINS];
        softmax8(p, 2.0f * BVAL, wu);
        softmax8_nm(wu, 1.0f - MIN_BW * KBINS, w_);
        cw[0] = -BVAL;
        float c = 0.0f;
#pragma unroll
        for (int k = 0; k < KBINS; k++) { c += w_[k] + MIN_BW; cw[k + 1] = 2.0f * BVAL * c - BVAL; }
        cw[KBINS] = BVAL;
    }
    {
        float hu[KBINS], h_[KBINS];
        softmax8(p + KBINS, 2.0f * BVAL, hu);
        softmax8_nm(hu, 1.0f - MIN_BW * KBINS, h_);
        ch[0] = -BVAL;
        float c = 0.0f;
#pragma unroll
        for (int k = 0; k < KBINS; k++) { c += h_[k] + MIN_BW; ch[k + 1] = 2.0f * BVAL * c - BVAL; }
        ch[KBINS] = BVAL;
    }

    float dv[KBINS + 1];
    {
        float de = MIN_D + softplusf(CPAD);
        dv[0] = de; dv[KBINS] = de;
#pragma unroll
        for (int j = 0; j < KBINS - 1; j++)
            dv[j + 1] = MIN_D + softplusf(softplusf(p[2 * KBINS + j]));
    }

    bool inside = (xin >= -BVAL) && (xin <= BVAL);
    float xc = fminf(fmaxf(xin, -BVAL), BVAL);

    float in_cw = cw[0], in_ch = ch[0];
    float in_w = cw[1] - cw[0], in_h = ch[1] - ch[0];
    float d0 = dv[0], d1 = dv[1];
#pragma unroll
    for (int k = 1; k < KBINS; k++) {
        if (xc >= cw[k]) {
            in_cw = cw[k]; in_ch = ch[k];
            in_w = cw[k + 1] - cw[k]; in_h = ch[k + 1] - ch[k];
            d0 = dv[k]; d1 = dv[k + 1];
        }
    }

    float invw = __fdividef(1.0f, in_w);
    float delta = in_h * invw;
    float th = (xc - in_cw) * invw;
    float tt = th * (1.0f - th);
    float num = in_h * (delta * th * th + d0 * tt);
    float den = delta + (d0 + d1 - 2.0f * delta) * tt;
    float outv = in_ch + __fdividef(num, den);
    float omt = 1.0f - th;
    float dnum = delta * delta * (d1 * th * th + 2.0f * delta * tt + d0 * omt * omt);
    float ld = __logf(dnum) - 2.0f * __logf(den);

    *ldo = inside ? ld : 0.0f;
    return inside ? outv : xin;
}

// block = 128 threads, each thread owns 2 batch elements (t and t+128 of a
// 256-element block tile) so every warp-uniform weight LDS feeds 2 FMAs.
__global__ __launch_bounds__(128, 2) void nsf_ar_kernel(
    const float* __restrict__ x, const float* __restrict__ init_param,
    const float* __restrict__ w1, const float* __restrict__ b1,
    const float* __restrict__ w2, const float* __restrict__ b2,
    const float* __restrict__ w3, const float* __restrict__ b3,
    float* __restrict__ zout, float* __restrict__ ldout, int write_ld)
{
    __shared__ float xs[256][33];     // x tile, padded
    __shared__ float hs[128][33];     // per-thread activation scratch (elem B)
    __shared__ float w1s[31][32];
    __shared__ float w2s[32][32];
    __shared__ float w3s[32][24];
    __shared__ float b1s[32], b2s[32], b3s[NP];

    const int t = threadIdx.x;
    const int b0 = blockIdx.x * 256;

    // stage x tile (coalesced float4 global reads, scalar smem writes)
    {
        const float4* gx = (const float4*)(x + (size_t)b0 * 32);
        for (int i = t; i < 256 * 8; i += 128) {
            float4 v = gx[i];
            int row = i >> 3, c4 = (i & 7) << 2;
            xs[row][c4 + 0] = v.x; xs[row][c4 + 1] = v.y;
            xs[row][c4 + 2] = v.z; xs[row][c4 + 3] = v.w;
        }
    }
    __syncthreads();

    const int ba = b0 + t;
    const int bb = b0 + 128 + t;
    const int ta = t, tb = 128 + t;

    float ldaccA, ldaccB;
    {
        float p[NP];
#pragma unroll
        for (int j = 0; j < NP; j++) p[j] = init_param[j];   // uniform broadcast
        float ld;
        zout[(size_t)ba * DIMN] = spline_fwd(xs[ta][0], p, &ld);
        ldaccA = ld;
        zout[(size_t)bb * DIMN] = spline_fwd(xs[tb][0], p, &ld);
        ldaccB = ld;
    }

    for (int l = 0; l < LNUM; l++) {
        __syncthreads();
        // stage layer-l weights (scalar, as in the 393us baseline)
        {
            float* w1f = &w1s[0][0];
            float* w2f = &w2s[0][0];
            for (int i = t; i < 31 * 32; i += 128) w1f[i] = w1[l * 992 + i];
            for (int i = t; i < 32 * 32; i += 128) w2f[i] = w2[l * 1024 + i];
            for (int i = t; i < 32 * 23; i += 128) {
                int r = i / 23, c = i - r * 23;
                w3s[r][c] = w3[l * 736 + i];
            }
            if (t < 32) { b1s[t] = b1[l * 32 + t]; b2s[t] = b2[l * 32 + t]; }
            if (t < NP) b3s[t] = b3[l * NP + t];
        }
        __syncthreads();

        // ---- h1 = tanh(x[:, :l+1] @ w1 + b1)  for both elements ----
        float h1a[HID], h1b[HID];
#pragma unroll
        for (int h = 0; h < HID; h++) { h1a[h] = b1s[h]; h1b[h] = b1s[h]; }
        for (int d = 0; d <= l; d++) {
            float xa = xs[ta][d];
            float xb = xs[tb][d];
#pragma unroll
            for (int h = 0; h < HID; h++) {
                float w = w1s[d][h];
                h1a[h] = fmaf(xa, w, h1a[h]);
                h1b[h] = fmaf(xb, w, h1b[h]);
            }
        }
#pragma unroll
        for (int h = 0; h < HID; h++) {
            h1a[h] = fast_tanh(h1a[h]);
            hs[t][h] = fast_tanh(h1b[h]);   // park elem-B activations in smem
        }

        // ---- h2 = tanh(h1 @ w2 + b2) ----
        float h2a[HID], h2b[HID];
#pragma unroll
        for (int h = 0; h < HID; h++) { h2a[h] = b2s[h]; h2b[h] = b2s[h]; }
#pragma unroll
        for (int d = 0; d < HID; d++) {
            float va = h1a[d];
            float vb = hs[t][d];
#pragma unroll
            for (int h = 0; h < HID; h++) {
                float w = w2s[d][h];
                h2a[h] = fmaf(va, w, h2a[h]);
                h2b[h] = fmaf(vb, w, h2b[h]);
            }
        }
#pragma unroll
        for (int h = 0; h < HID; h++) {
            h2a[h] = fast_tanh(h2a[h]);
            hs[t][h] = fast_tanh(h2b[h]);   // reuse scratch (h1b dead now)
        }

        // ---- p = h2 @ w3 + b3 ----
        float pa[NP], pb[NP];
#pragma unroll
        for (int j = 0; j < NP; j++) { pa[j] = b3s[j]; pb[j] = b3s[j]; }
#pragma unroll
        for (int d = 0; d < HID; d++) {
            float va = h2a[d];
            float vb = hs[t][d];
#pragma unroll
            for (int j = 0; j < NP; j++) {
                float w = w3s[d][j];
                pa[j] = fmaf(va, w, pa[j]);
                pb[j] = fmaf(vb, w, pb[j]);
            }
        }

        // ---- spline for dim l+1, both elements ----
        float ld;
        zout[(size_t)ba * DIMN + l + 1] = spline_fwd(xs[ta][l + 1], pa, &ld);
        ldaccA += ld;
        zout[(size_t)bb * DIMN + l + 1] = spline_fwd(xs[tb][l + 1], pb, &ld);
        ldaccB += ld;
    }

    if (write_ld) { ldout[ba] = ldaccA; ldout[bb] = ldaccB; }
}

extern "C" void kernel_launch(void* const* d_in, const int* in_sizes, int n_in,
                              void* d_out, int out_size) {
    const float* x          = (const float*)d_in[0];
    const float* init_param = (const float*)d_in[1];
    const float* w1 = (const float*)d_in[2];
    const float* b1 = (const float*)d_in[3];
    const float* w2 = (const float*)d_in[4];
    const float* b2 = (const float*)d_in[5];
    const float* w3 = (const float*)d_in[6];
    const float* b3 = (const float*)d_in[7];

    float* out = (float*)d_out;
    int write_ld = (out_size >= BATCH * DIMN + BATCH) ? 1 : 0;

    nsf_ar_kernel<<<BATCH / 256, 128>>>(x, init_param, w1, b1, w2, b2, w3, b3,
                                        out, out + (size_t)BATCH * DIMN, write_ld);
}